// round 14
// baseline (speedup 1.0000x reference)
#include <cuda_runtime.h>
#include <math.h>

#define NUM_E   100000
#define HDIM    200
#define H4      50          // HDIM / 4
#define NEDGE   1000000
#define BATCH   512
#define RRELU_SLOPE 0.2291666666666667f
#define BN_EPS  1e-5f

#define AGG_OFF ((long long)NUM_E * HDIM)   // agg/h2 region starts at out + 20M floats

// ---------------- tiny device globals ONLY (~1.21 MB; no static ctor) ----------------
__device__ float g_deg  [NUM_E];
__device__ float g_gate [NUM_E];
__device__ float g_q    [BATCH * HDIM];
__device__ float g_stats[8];
__device__ int   g_is64;

// ---------------- helpers ----------------
__device__ __forceinline__ long long ld_idx(const void* p, long long i, int is64) {
    if (is64) return ((const long long*)p)[i];
    return (long long)((const int*)p)[i];
}

__device__ __forceinline__ void red_add_v4(float* addr, float4 v) {
    asm volatile("red.global.add.v4.f32 [%0], {%1,%2,%3,%4};"
                 :: "l"(addr), "f"(v.x), "f"(v.y), "f"(v.z), "f"(v.w) : "memory");
}

__device__ __forceinline__ float warp_sum(float v) {
    #pragma unroll
    for (int o = 16; o > 0; o >>= 1) v += __shfl_xor_sync(0xffffffffu, v, o);
    return v;
}

__device__ __forceinline__ float rrelu(float x) {
    return x >= 0.0f ? x : x * RRELU_SLOPE;
}

// packed fp32x2 FMA: d = a*b + d (lanewise on two fp32 in a 64-bit reg)
__device__ __forceinline__ void fma2(unsigned long long& d,
                                     unsigned long long a, unsigned long long b) {
    asm("fma.rn.f32x2 %0, %1, %2, %0;" : "+l"(d) : "l"(a), "l"(b));
}
__device__ __forceinline__ float f2_lo(unsigned long long v) {
    return __uint_as_float((unsigned)(v & 0xffffffffu));
}
__device__ __forceinline__ float f2_hi(unsigned long long v) {
    return __uint_as_float((unsigned)(v >> 32));
}

// ---------------- index width detection (int32 vs int64) ----------------
__global__ __launch_bounds__(32) void k_detect(const unsigned int* w) {
    if (threadIdx.x == 0) {
        int is64 = 1;
        for (int i = 0; i < 64; i++) {
            if (w[2 * i + 1] != 0u) { is64 = 0; break; }
        }
        g_is64 = is64;
    }
}

// ---------------- zero kernels ----------------
__global__ __launch_bounds__(256) void k_zero_init(float* __restrict__ agg) {
    long long i = (long long)blockIdx.x * blockDim.x + threadIdx.x;
    float4 z = make_float4(0.f, 0.f, 0.f, 0.f);
    if (i < (long long)NUM_E * H4) ((float4*)agg)[i] = z;
    if (i < NUM_E / 4)             ((float4*)g_deg)[i] = z;
    if (i < 2)                     ((float4*)g_stats)[i] = z;
}

__global__ __launch_bounds__(256) void k_zero_agg(float* __restrict__ agg) {
    long long i = (long long)blockIdx.x * blockDim.x + threadIdx.x;
    if (i < (long long)NUM_E * H4)
        ((float4*)agg)[i] = make_float4(0.f, 0.f, 0.f, 0.f);
}

// ---------------- edge scatter (warp per edge): agg[dst] += h[src] + rel[etype] ----------------
__global__ __launch_bounds__(256) void k_edges(const void* srcp, const void* dstp, const void* etp,
                                               const float* __restrict__ rel_emb,
                                               const float* __restrict__ hsrc,
                                               float* __restrict__ agg, int do_deg) {
    long long w = ((long long)blockIdx.x * blockDim.x + threadIdx.x) >> 5;
    int lane = threadIdx.x & 31;
    if (w >= NEDGE) return;
    int is64 = g_is64;
    long long d = ld_idx(dstp, w, is64);
    long long t = ld_idx(etp, w, is64);
    long long s = ld_idx(srcp, w, is64);
    if (do_deg && lane == 0) atomicAdd(&g_deg[d], 1.0f);
    const float4* r4 = (const float4*)(rel_emb + t * HDIM);
    const float4* h4 = (const float4*)(hsrc + s * HDIM);
    float* agb = agg + d * HDIM;
    #pragma unroll
    for (int u = 0; u < 2; ++u) {
        int c = lane + u * 32;
        if (c < H4) {
            float4 v = h4[c], r = r4[c];
            v.x += r.x; v.y += r.y; v.z += r.z; v.w += r.w;
            red_add_v4(agb + 4 * c, v);
        }
    }
}

// ---------------- fused node transform (f32x2 packed): hout = rrelu(A@Wn + H@Wl)
// A = agg/max(deg,1), H = hin. Matrix-paired f32x2: acc2[r][c] = {N_partial, L_partial};
// smem holds interleaved pairs: AH[r][k]=(a,h), W[c][k]=(wn,wl) (transposed, 80B rows).
// 32-row tile, 400 threads (tx0 0..49 -> strided cols {tx0+50i}, ty 0..7 -> 4 rows),
// BK=8 double-buffered W, 1 sync/iter. In-place safe over agg (fully staged first).
__global__ __launch_bounds__(400, 2) void k_transform(const float* __restrict__ hin,
                                                      const float* __restrict__ Wn,
                                                      const float* __restrict__ Wl,
                                                      const float* __restrict__ agg,
                                                      float* __restrict__ hout) {
    extern __shared__ float sm[];
    float* AH = sm;                   // 32 rows x 400 floats (200 (a,h) pairs), row 1600B
    float* Wp = AH + 32 * 400;        // [2 buf][200 c-rows][20 floats] (8 (wn,wl) pairs + pad), row 80B

    const int tid = threadIdx.x;
    const int tx0 = tid % 50;
    const int ty  = tid / 50;         // 0..7
    const long long base = (long long)blockIdx.x * 32;

    // stage AH interleaved: (a*inv, h) pairs
    for (int i = tid; i < 32 * H4; i += 400) {
        int r = i / H4, c4 = i % H4;
        long long n = base + r;
        float inv = 1.0f / fmaxf(g_deg[n], 1.0f);
        float4 a = *(const float4*)(agg + n * HDIM + 4 * c4);
        float4 h = *(const float4*)(hin + n * HDIM + 4 * c4);
        *(float4*)(AH + r * 400 + c4 * 8)     = make_float4(a.x * inv, h.x, a.y * inv, h.y);
        *(float4*)(AH + r * 400 + c4 * 8 + 4) = make_float4(a.z * inv, h.z, a.w * inv, h.w);
    }

    // stage W k-tile kt into buffer buf: interleaved transposed pairs W[c][k]=(wn,wl)
    auto stageW = [&](int kt, int buf) {
        int k  = tid / 50;            // 0..7
        int c4 = tid % 50;
        float4 wn = *(const float4*)(Wn + (kt * 8 + k) * HDIM + 4 * c4);
        float4 wl = *(const float4*)(Wl + (kt * 8 + k) * HDIM + 4 * c4);
        float* Wb = Wp + buf * 4000;
        *(float2*)(Wb + (4 * c4 + 0) * 20 + k * 2) = make_float2(wn.x, wl.x);
        *(float2*)(Wb + (4 * c4 + 1) * 20 + k * 2) = make_float2(wn.y, wl.y);
        *(float2*)(Wb + (4 * c4 + 2) * 20 + k * 2) = make_float2(wn.z, wl.z);
        *(float2*)(Wb + (4 * c4 + 3) * 20 + k * 2) = make_float2(wn.w, wl.w);
    };

    stageW(0, 0);
    __syncthreads();

    unsigned long long acc2[16];
    #pragma unroll
    for (int i = 0; i < 16; i++) acc2[i] = 0ull;

    for (int kt = 0; kt < 25; ++kt) {
        const int cur = kt & 1;
        if (kt < 24) stageW(kt + 1, cur ^ 1);   // overlaps with compute below

        const float* Wc = Wp + cur * 4000;

        #pragma unroll
        for (int kp = 0; kp < 4; ++kp) {        // 4 k-pairs per BK=8 tile
            ulonglong2 ah0 = *(const ulonglong2*)(AH + (ty * 4 + 0) * 400 + kt * 16 + kp * 4);
            ulonglong2 ah1 = *(const ulonglong2*)(AH + (ty * 4 + 1) * 400 + kt * 16 + kp * 4);
            ulonglong2 ah2 = *(const ulonglong2*)(AH + (ty * 4 + 2) * 400 + kt * 16 + kp * 4);
            ulonglong2 ah3 = *(const ulonglong2*)(AH + (ty * 4 + 3) * 400 + kt * 16 + kp * 4);
            #pragma unroll
            for (int ci = 0; ci < 4; ++ci) {
                ulonglong2 wv = *(const ulonglong2*)(Wc + (tx0 + 50 * ci) * 20 + kp * 4);
                fma2(acc2[0 * 4 + ci], ah0.x, wv.x); fma2(acc2[0 * 4 + ci], ah0.y, wv.y);
                fma2(acc2[1 * 4 + ci], ah1.x, wv.x); fma2(acc2[1 * 4 + ci], ah1.y, wv.y);
                fma2(acc2[2 * 4 + ci], ah2.x, wv.x); fma2(acc2[2 * 4 + ci], ah2.y, wv.y);
                fma2(acc2[3 * 4 + ci], ah3.x, wv.x); fma2(acc2[3 * 4 + ci], ah3.y, wv.y);
            }
        }
        __syncthreads();
    }

    #pragma unroll
    for (int rr = 0; rr < 4; ++rr) {
        long long n = base + ty * 4 + rr;
        #pragma unroll
        for (int ci = 0; ci < 4; ++ci) {
            unsigned long long v = acc2[rr * 4 + ci];
            hout[n * HDIM + tx0 + 50 * ci] = rrelu(f2_lo(v) + f2_hi(v));
        }
    }
}

// ---------------- gate scalar per node ----------------
__global__ __launch_bounds__(256) void k_gatepre(const float* __restrict__ theta,
                                                 const float* __restrict__ gw,
                                                 const float* __restrict__ gb) {
    long long w = ((long long)blockIdx.x * blockDim.x + threadIdx.x) >> 5;
    int lane = threadIdx.x & 31;
    if (w >= NUM_E) return;
    const float4* t4 = (const float4*)(theta + w * HDIM);
    const float4* w4 = (const float4*)gw;
    float p = 0.f;
    #pragma unroll
    for (int u = 0; u < 2; ++u) {
        int c = lane + u * 32;
        if (c < H4) {
            float4 a = t4[c], b = w4[c];
            p += a.x * b.x + a.y * b.y + a.z * b.z + a.w * b.w;
        }
    }
    p = warp_sum(p);
    if (lane == 0) g_gate[w] = 1.0f / (1.0f + expf(-(p + gb[0])));
}

// ---------------- blend + transpose: hT[c][n] ----------------
__global__ __launch_bounds__(256) void k_blendT(const float* __restrict__ h2,
                                                const float* __restrict__ ent,
                                                float* __restrict__ hT) {
    __shared__ float sm[32 * 201];
    const int tid = threadIdx.x;
    const long long n0 = (long long)blockIdx.x * 32;

    for (int i = tid; i < 32 * H4; i += 256) {
        int r = i / H4, c4 = i % H4;
        long long n = n0 + r;
        float g = g_gate[n], og = 1.0f - g;
        float4 h = *(const float4*)(h2 + n * HDIM + 4 * c4);
        float4 e = *(const float4*)(ent + n * HDIM + 4 * c4);
        sm[r * 201 + 4 * c4 + 0] = g * h.x + og * e.x;
        sm[r * 201 + 4 * c4 + 1] = g * h.y + og * e.y;
        sm[r * 201 + 4 * c4 + 2] = g * h.z + og * e.z;
        sm[r * 201 + 4 * c4 + 3] = g * h.w + og * e.w;
    }
    __syncthreads();

    for (int i = tid; i < HDIM * 32; i += 256) {
        int r = i & 31;
        int c = i >> 5;
        hT[(long long)c * NUM_E + n0 + r] = sm[r * 201 + c];
    }
}

// ---------------- BN batch statistics ----------------
__global__ __launch_bounds__(256) void k_bnstats(const float* __restrict__ hT,
                                                 const float* __restrict__ rel_emb,
                                                 const float* __restrict__ freq,
                                                 const void* sidx, const void* ridx) {
    int b = blockIdx.x;
    int tid = threadIdx.x;
    int lane = tid & 31;
    int is64 = g_is64;
    long long s = ld_idx(sidx, b, is64);
    long long r = ld_idx(ridx, b, is64);
    float e = 0.f, rr = 0.f, f = 0.f;
    if (tid < HDIM) {
        e  = hT[(long long)tid * NUM_E + s];
        rr = rel_emb[r * HDIM + tid];
        f  = freq[(long long)b * HDIM + tid];
    }
    float s0 = warp_sum(e),  s1 = warp_sum(e * e);
    float s2 = warp_sum(rr), s3 = warp_sum(rr * rr);
    float s4 = warp_sum(f),  s5 = warp_sum(f * f);
    if (lane == 0) {
        atomicAdd(&g_stats[0], s0); atomicAdd(&g_stats[1], s1);
        atomicAdd(&g_stats[2], s2); atomicAdd(&g_stats[3], s3);
        atomicAdd(&g_stats[4], s4); atomicAdd(&g_stats[5], s5);
    }
}

// ---------------- BN + relu + conv1d(3->1) -> g_q ----------------
__global__ __launch_bounds__(256) void k_q(const float* __restrict__ hT,
                                           const float* __restrict__ rel_emb,
                                           const float* __restrict__ freq,
                                           const void* sidx, const void* ridx,
                                           const float* __restrict__ bng, const float* __restrict__ bnb,
                                           const float* __restrict__ cw,  const float* __restrict__ cb) {
    int idx = blockIdx.x * blockDim.x + threadIdx.x;
    if (idx >= BATCH * HDIM) return;
    int b = idx / HDIM, h = idx % HDIM;
    int is64 = g_is64;
    long long s = ld_idx(sidx, b, is64);
    long long r = ld_idx(ridx, b, is64);
    const float inv = 1.0f / (float)(BATCH * HDIM);
    float m0 = g_stats[0] * inv, m1 = g_stats[2] * inv, m2 = g_stats[4] * inv;
    float v0 = g_stats[1] * inv - m0 * m0;
    float v1 = g_stats[3] * inv - m1 * m1;
    float v2 = g_stats[5] * inv - m2 * m2;
    float rs0 = rsqrtf(v0 + BN_EPS), rs1 = rsqrtf(v1 + BN_EPS), rs2 = rsqrtf(v2 + BN_EPS);
    float x0 = hT[(long long)h * NUM_E + s];
    float x1 = rel_emb[r * HDIM + h];
    float x2 = freq[idx];
    float y0 = fmaxf((x0 - m0) * rs0 * bng[0] + bnb[0], 0.f);
    float y1 = fmaxf((x1 - m1) * rs1 * bng[1] + bnb[1], 0.f);
    float y2 = fmaxf((x2 - m2) * rs2 * bng[2] + bnb[2], 0.f);
    g_q[idx] = y0 * cw[0] + y1 * cw[1] + y2 * cw[2] + cb[0];
}

// ---------------- scores = q @ h_final^T, IN PLACE over hT (panel-exclusive blocks) -----------
// f32x2 packed over k (even/odd partial sums, horizontal add at the end).
// h_sm transposed [j][k] (202-float rows, conflict-free LDS.64); q_sm [bi][k] (204-pad).
// Block owns a 64-col panel: stages hT[:,panel] first, then writes out[:,panel].
__global__ __launch_bounds__(256, 2) void k_scores(float* __restrict__ out) {
    extern __shared__ float smem[];
    float* h_sm = smem;               // [j=64][202]
    float* q_sm = smem + 64 * 202;    // [bi=64][204]

    const int t = threadIdx.x;
    const long long n0 = (long long)blockIdx.x * 64;
    const int jmax = (NUM_E - n0 >= 64) ? 64 : (int)(NUM_E - n0);

    // stage hT panel transposed into h_sm[j][k] (coalesced reads along n)
    for (int i = t; i < HDIM * 16; i += 256) {
        int c = i / 16, j4 = i % 16;
        float4 v = make_float4(0.f, 0.f, 0.f, 0.f);
        if (j4 * 4 < jmax)
            v = *(const float4*)(out + (long long)c * NUM_E + n0 + j4 * 4);
        h_sm[(j4 * 4 + 0) * 202 + c] = v.x;
        h_sm[(j4 * 4 + 1) * 202 + c] = v.y;
        h_sm[(j4 * 4 + 2) * 202 + c] = v.z;
        h_sm[(j4 * 4 + 3) * 202 + c] = v.w;
    }

    const int tx = t & 15;   // n-lane; cols {tx + 16*ci}
    const int ty = t >> 4;   // b-group of 4

    for (int bc = 0; bc < BATCH / 64; ++bc) {
        const int b0 = bc * 64;
        __syncthreads();     // (first iter: also covers h_sm visibility)
        for (int i = t; i < 64 * 50; i += 256) {
            int bi = i / 50, k4 = i % 50;
            float4 v = *(const float4*)(g_q + (b0 + bi) * HDIM + k4 * 4);
            *(float4*)&q_sm[bi * 204 + k4 * 4] = v;
        }
        __syncthreads();

        unsigned long long acc2[16];
        #pragma unroll
        for (int i = 0; i < 16; i++) acc2[i] = 0ull;

        for (int k4 = 0; k4 < 50; ++k4) {
            ulonglong2 q0 = *(const ulonglong2*)&q_sm[(ty * 4 + 0) * 204 + k4 * 4];
            ulonglong2 q1 = *(const ulonglong2*)&q_sm[(ty * 4 + 1) * 204 + k4 * 4];
            ulonglong2 q2 = *(const ulonglong2*)&q_sm[(ty * 4 + 2) * 204 + k4 * 4];
            ulonglong2 q3 = *(const ulonglong2*)&q_sm[(ty * 4 + 3) * 204 + k4 * 4];
            #pragma unroll
            for (int ci = 0; ci < 4; ++ci) {
                const float* hrow = h_sm + (tx + 16 * ci) * 202 + k4 * 4;
                unsigned long long h01 = *(const unsigned long long*)(hrow);
                unsigned long long h23 = *(const unsigned long long*)(hrow + 2);
                fma2(acc2[0 * 4 + ci], q0.x, h01); fma2(acc2[0 * 4 + ci], q0.y, h23);
                fma2(acc2[1 * 4 + ci], q1.x, h01); fma2(acc2[1 * 4 + ci], q1.y, h23);
                fma2(acc2[2 * 4 + ci], q2.x, h01); fma2(acc2[2 * 4 + ci], q2.y, h23);
                fma2(acc2[3 * 4 + ci], q3.x, h01); fma2(acc2[3 * 4 + ci], q3.y, h23);
            }
        }

        #pragma unroll
        for (int a = 0; a < 4; ++a) {
            long long b = b0 + ty * 4 + a;
            #pragma unroll
            for (int ci = 0; ci < 4; ++ci) {
                long long n = n0 + tx + 16 * ci;
                if (n < NUM_E) {
                    unsigned long long v = acc2[a * 4 + ci];
                    out[b * NUM_E + n] = f2_lo(v) + f2_hi(v);
                }
            }
        }
    }
}

// ---------------- launch ----------------
extern "C" void kernel_launch(void* const* d_in, const int* in_sizes, int n_in,
                              void* d_out, int out_size) {
    const float* ent  = (const float*)d_in[0];
    const float* rel  = (const float*)d_in[1];
    const float* Wn1  = (const float*)d_in[2];
    const float* Wl1  = (const float*)d_in[3];
    const float* Wn2  = (const float*)d_in[4];
    const float* Wl2  = (const float*)d_in[5];
    const float* gth  = (const float*)d_in[6];
    const float* gw   = (const float*)d_in[7];
    const float* gb   = (const float*)d_in[8];
    const float* bng  = (const float*)d_in[9];
    const float* bnb  = (const float*)d_in[10];
    const float* cw   = (const float*)d_in[11];
    const float* cb   = (const float*)d_in[12];
    const float* freq = (const float*)d_in[13];
    const void*  src  = d_in[14];
    const void*  dst  = d_in[15];
    const void*  etp  = d_in[16];
    const void*  sidx = d_in[17];
    const void*  ridx = d_in[18];
    float* out = (float*)d_out;

    float* h1  = out;             // [0, 20M)
    float* agg = out + AGG_OFF;   // [20M, 40M); later h2 in place
    float* hT  = out;             // [0, 20M), transposed h_final (after h1 dead)

    const int TRANS_SMEM  = (32 * 400 + 2 * 200 * 20) * (int)sizeof(float);   // 83.2 KB
    const int SCORES_SMEM = (64 * 202 + 64 * 204) * (int)sizeof(float);       // 103.9 KB
    cudaFuncSetAttribute(k_transform, cudaFuncAttributeMaxDynamicSharedMemorySize, TRANS_SMEM);
    cudaFuncSetAttribute(k_scores,    cudaFuncAttributeMaxDynamicSharedMemorySize, SCORES_SMEM);

    const int zgrid = (NUM_E * H4 + 255) / 256;

    k_zero_init<<<zgrid, 256>>>(agg);
    k_detect<<<1, 32>>>((const unsigned int*)src);

    // layer 1
    k_edges<<<NEDGE / 8, 256>>>(src, dst, etp, rel, ent, agg, 1);
    k_transform<<<NUM_E / 32, 400, TRANS_SMEM>>>(ent, Wn1, Wl1, agg, h1);

    // layer 2 (h2 in place over agg)
    k_zero_agg<<<zgrid, 256>>>(agg);
    k_edges<<<NEDGE / 8, 256>>>(src, dst, etp, rel, h1, agg, 0);
    k_transform<<<NUM_E / 32, 400, TRANS_SMEM>>>(h1, Wn2, Wl2, agg, agg);

    // gate + transposed blend into hT = out[0,20M)
    k_gatepre<<<NUM_E / 8, 256>>>(gth, gw, gb);
    k_blendT<<<NUM_E / 32, 256>>>(agg /*h2*/, ent, hT);

    // ConvE head
    k_bnstats<<<BATCH, 256>>>(hT, rel, freq, sidx, ridx);
    k_q<<<(BATCH * HDIM + 255) / 256, 256>>>(hT, rel, freq, sidx, ridx, bng, bnb, cw, cb);

    // scores in place over the whole output (panel-exclusive blocks)
    k_scores<<<(NUM_E + 63) / 64, 256, SCORES_SMEM>>>(out);
}

// round 15
// speedup vs baseline: 1.0957x; 1.0957x over previous
#include <cuda_runtime.h>
#include <math.h>

#define NUM_E   100000
#define HDIM    200
#define H4      50          // HDIM / 4
#define NEDGE   1000000
#define BATCH   512
#define RRELU_SLOPE 0.2291666666666667f
#define BN_EPS  1e-5f

#define AGG_OFF ((long long)NUM_E * HDIM)   // agg/h2 region starts at out + 20M floats

// ---------------- tiny device globals ONLY (~1.21 MB; no static ctor) ----------------
__device__ float g_deg  [NUM_E];
__device__ float g_gate [NUM_E];
__device__ float g_q    [BATCH * HDIM];
__device__ float g_stats[8];
__device__ int   g_is64;

// ---------------- helpers ----------------
__device__ __forceinline__ long long ld_idx(const void* p, long long i, int is64) {
    if (is64) return ((const long long*)p)[i];
    return (long long)((const int*)p)[i];
}

__device__ __forceinline__ void red_add_v4(float* addr, float4 v) {
    asm volatile("red.global.add.v4.f32 [%0], {%1,%2,%3,%4};"
                 :: "l"(addr), "f"(v.x), "f"(v.y), "f"(v.z), "f"(v.w) : "memory");
}

__device__ __forceinline__ float warp_sum(float v) {
    #pragma unroll
    for (int o = 16; o > 0; o >>= 1) v += __shfl_xor_sync(0xffffffffu, v, o);
    return v;
}

__device__ __forceinline__ float rrelu(float x) {
    return x >= 0.0f ? x : x * RRELU_SLOPE;
}

// packed fp32x2 FMA: d = a*b + d (lanewise on two fp32 in a 64-bit reg)
__device__ __forceinline__ void fma2(unsigned long long& d,
                                     unsigned long long a, unsigned long long b) {
    asm("fma.rn.f32x2 %0, %1, %2, %0;" : "+l"(d) : "l"(a), "l"(b));
}
__device__ __forceinline__ float f2_lo(unsigned long long v) {
    return __uint_as_float((unsigned)(v & 0xffffffffu));
}
__device__ __forceinline__ float f2_hi(unsigned long long v) {
    return __uint_as_float((unsigned)(v >> 32));
}

// ---------------- index width detection (int32 vs int64) ----------------
__global__ __launch_bounds__(32) void k_detect(const unsigned int* w) {
    if (threadIdx.x == 0) {
        int is64 = 1;
        for (int i = 0; i < 64; i++) {
            if (w[2 * i + 1] != 0u) { is64 = 0; break; }
        }
        g_is64 = is64;
    }
}

// ---------------- zero kernels ----------------
__global__ __launch_bounds__(256) void k_zero_init(float* __restrict__ agg) {
    long long i = (long long)blockIdx.x * blockDim.x + threadIdx.x;
    float4 z = make_float4(0.f, 0.f, 0.f, 0.f);
    if (i < (long long)NUM_E * H4) ((float4*)agg)[i] = z;
    if (i < NUM_E / 4)             ((float4*)g_deg)[i] = z;
    if (i < 2)                     ((float4*)g_stats)[i] = z;
}

__global__ __launch_bounds__(256) void k_zero_agg(float* __restrict__ agg) {
    long long i = (long long)blockIdx.x * blockDim.x + threadIdx.x;
    if (i < (long long)NUM_E * H4)
        ((float4*)agg)[i] = make_float4(0.f, 0.f, 0.f, 0.f);
}

// ---------------- edge scatter (warp per edge): agg[dst] += h[src] + rel[etype] ----------------
__global__ __launch_bounds__(256) void k_edges(const void* srcp, const void* dstp, const void* etp,
                                               const float* __restrict__ rel_emb,
                                               const float* __restrict__ hsrc,
                                               float* __restrict__ agg, int do_deg) {
    long long w = ((long long)blockIdx.x * blockDim.x + threadIdx.x) >> 5;
    int lane = threadIdx.x & 31;
    if (w >= NEDGE) return;
    int is64 = g_is64;
    long long d = ld_idx(dstp, w, is64);
    long long t = ld_idx(etp, w, is64);
    long long s = ld_idx(srcp, w, is64);
    if (do_deg && lane == 0) atomicAdd(&g_deg[d], 1.0f);
    const float4* r4 = (const float4*)(rel_emb + t * HDIM);
    const float4* h4 = (const float4*)(hsrc + s * HDIM);
    float* agb = agg + d * HDIM;
    #pragma unroll
    for (int u = 0; u < 2; ++u) {
        int c = lane + u * 32;
        if (c < H4) {
            float4 v = h4[c], r = r4[c];
            v.x += r.x; v.y += r.y; v.z += r.z; v.w += r.w;
            red_add_v4(agb + 4 * c, v);
        }
    }
}

// ---------------- fused node transform (f32x2, conflict-free W): hout = rrelu(A@Wn + H@Wl)
// Matrix-paired f32x2: acc2[r][c] = {N_partial, L_partial}.
// AH[r][k] = (a*inv, h) pairs, rows of 400 floats (loads are warp-broadcast).
// W2[k][c] = (wn, wl) float2, k-row-major rows of 400 floats: inner load word offset 2*tx0
//   -> each half-warp hits all 32 banks exactly once (conflict-free LDS.64).
// 32-row tile, 400 threads, BK=8 double-buffered, 1 sync/iter. In-place safe over agg.
__global__ __launch_bounds__(400, 2) void k_transform(const float* __restrict__ hin,
                                                      const float* __restrict__ Wn,
                                                      const float* __restrict__ Wl,
                                                      const float* __restrict__ agg,
                                                      float* __restrict__ hout) {
    extern __shared__ float sm[];
    float* AH = sm;                   // [32][400]: 200 (a,h) pairs per row
    float* Wp = AH + 32 * 400;        // [2 buf][8 k][400]: 200 (wn,wl) pairs per k-row

    const int tid = threadIdx.x;
    const int tx0 = tid % 50;
    const int ty  = tid / 50;         // 0..7
    const long long base = (long long)blockIdx.x * 32;

    // stage AH interleaved: (a*inv, h) pairs
    for (int i = tid; i < 32 * H4; i += 400) {
        int r = i / H4, c4 = i % H4;
        long long n = base + r;
        float inv = 1.0f / fmaxf(g_deg[n], 1.0f);
        float4 a = *(const float4*)(agg + n * HDIM + 4 * c4);
        float4 h = *(const float4*)(hin + n * HDIM + 4 * c4);
        *(float4*)(AH + r * 400 + c4 * 8)     = make_float4(a.x * inv, h.x, a.y * inv, h.y);
        *(float4*)(AH + r * 400 + c4 * 8 + 4) = make_float4(a.z * inv, h.z, a.w * inv, h.w);
    }

    // stage W k-tile kt into buffer buf: W2[k][c]=(wn,wl), k-row-major
    auto stageW = [&](int kt, int buf) {
        int k  = tid / 50;            // 0..7
        int c4 = tid % 50;
        float4 wn = *(const float4*)(Wn + (kt * 8 + k) * HDIM + 4 * c4);
        float4 wl = *(const float4*)(Wl + (kt * 8 + k) * HDIM + 4 * c4);
        float* Wb = Wp + buf * 3200 + k * 400 + 8 * c4;
        *(float4*)(Wb)     = make_float4(wn.x, wl.x, wn.y, wl.y);
        *(float4*)(Wb + 4) = make_float4(wn.z, wl.z, wn.w, wl.w);
    };

    stageW(0, 0);
    __syncthreads();

    unsigned long long acc2[16];
    #pragma unroll
    for (int i = 0; i < 16; i++) acc2[i] = 0ull;

    for (int kt = 0; kt < 25; ++kt) {
        const int cur = kt & 1;
        if (kt < 24) stageW(kt + 1, cur ^ 1);   // overlaps with compute below

        const float* Wc = Wp + cur * 3200;

        #pragma unroll
        for (int g = 0; g < 4; ++g) {           // 4 k-pairs per BK=8 tile
            // AH pairs for k = kt*8+2g and +1 (warp-broadcast LDS.128)
            ulonglong2 ah0 = *(const ulonglong2*)(AH + (ty * 4 + 0) * 400 + kt * 16 + g * 4);
            ulonglong2 ah1 = *(const ulonglong2*)(AH + (ty * 4 + 1) * 400 + kt * 16 + g * 4);
            ulonglong2 ah2 = *(const ulonglong2*)(AH + (ty * 4 + 2) * 400 + kt * 16 + g * 4);
            ulonglong2 ah3 = *(const ulonglong2*)(AH + (ty * 4 + 3) * 400 + kt * 16 + g * 4);
            #pragma unroll
            for (int ci = 0; ci < 4; ++ci) {
                const int cw = (tx0 + 50 * ci) * 2;
                unsigned long long w0 = *(const unsigned long long*)(Wc + (g * 2 + 0) * 400 + cw);
                unsigned long long w1 = *(const unsigned long long*)(Wc + (g * 2 + 1) * 400 + cw);
                fma2(acc2[0 * 4 + ci], ah0.x, w0); fma2(acc2[0 * 4 + ci], ah0.y, w1);
                fma2(acc2[1 * 4 + ci], ah1.x, w0); fma2(acc2[1 * 4 + ci], ah1.y, w1);
                fma2(acc2[2 * 4 + ci], ah2.x, w0); fma2(acc2[2 * 4 + ci], ah2.y, w1);
                fma2(acc2[3 * 4 + ci], ah3.x, w0); fma2(acc2[3 * 4 + ci], ah3.y, w1);
            }
        }
        __syncthreads();
    }

    #pragma unroll
    for (int rr = 0; rr < 4; ++rr) {
        long long n = base + ty * 4 + rr;
        #pragma unroll
        for (int ci = 0; ci < 4; ++ci) {
            unsigned long long v = acc2[rr * 4 + ci];
            hout[n * HDIM + tx0 + 50 * ci] = rrelu(f2_lo(v) + f2_hi(v));
        }
    }
}

// ---------------- gate scalar per node ----------------
__global__ __launch_bounds__(256) void k_gatepre(const float* __restrict__ theta,
                                                 const float* __restrict__ gw,
                                                 const float* __restrict__ gb) {
    long long w = ((long long)blockIdx.x * blockDim.x + threadIdx.x) >> 5;
    int lane = threadIdx.x & 31;
    if (w >= NUM_E) return;
    const float4* t4 = (const float4*)(theta + w * HDIM);
    const float4* w4 = (const float4*)gw;
    float p = 0.f;
    #pragma unroll
    for (int u = 0; u < 2; ++u) {
        int c = lane + u * 32;
        if (c < H4) {
            float4 a = t4[c], b = w4[c];
            p += a.x * b.x + a.y * b.y + a.z * b.z + a.w * b.w;
        }
    }
    p = warp_sum(p);
    if (lane == 0) g_gate[w] = 1.0f / (1.0f + expf(-(p + gb[0])));
}

// ---------------- blend + transpose: hT[c][n] ----------------
__global__ __launch_bounds__(256) void k_blendT(const float* __restrict__ h2,
                                                const float* __restrict__ ent,
                                                float* __restrict__ hT) {
    __shared__ float sm[32 * 201];
    const int tid = threadIdx.x;
    const long long n0 = (long long)blockIdx.x * 32;

    for (int i = tid; i < 32 * H4; i += 256) {
        int r = i / H4, c4 = i % H4;
        long long n = n0 + r;
        float g = g_gate[n], og = 1.0f - g;
        float4 h = *(const float4*)(h2 + n * HDIM + 4 * c4);
        float4 e = *(const float4*)(ent + n * HDIM + 4 * c4);
        sm[r * 201 + 4 * c4 + 0] = g * h.x + og * e.x;
        sm[r * 201 + 4 * c4 + 1] = g * h.y + og * e.y;
        sm[r * 201 + 4 * c4 + 2] = g * h.z + og * e.z;
        sm[r * 201 + 4 * c4 + 3] = g * h.w + og * e.w;
    }
    __syncthreads();

    for (int i = tid; i < HDIM * 32; i += 256) {
        int r = i & 31;
        int c = i >> 5;
        hT[(long long)c * NUM_E + n0 + r] = sm[r * 201 + c];
    }
}

// ---------------- BN batch statistics ----------------
__global__ __launch_bounds__(256) void k_bnstats(const float* __restrict__ hT,
                                                 const float* __restrict__ rel_emb,
                                                 const float* __restrict__ freq,
                                                 const void* sidx, const void* ridx) {
    int b = blockIdx.x;
    int tid = threadIdx.x;
    int lane = tid & 31;
    int is64 = g_is64;
    long long s = ld_idx(sidx, b, is64);
    long long r = ld_idx(ridx, b, is64);
    float e = 0.f, rr = 0.f, f = 0.f;
    if (tid < HDIM) {
        e  = hT[(long long)tid * NUM_E + s];
        rr = rel_emb[r * HDIM + tid];
        f  = freq[(long long)b * HDIM + tid];
    }
    float s0 = warp_sum(e),  s1 = warp_sum(e * e);
    float s2 = warp_sum(rr), s3 = warp_sum(rr * rr);
    float s4 = warp_sum(f),  s5 = warp_sum(f * f);
    if (lane == 0) {
        atomicAdd(&g_stats[0], s0); atomicAdd(&g_stats[1], s1);
        atomicAdd(&g_stats[2], s2); atomicAdd(&g_stats[3], s3);
        atomicAdd(&g_stats[4], s4); atomicAdd(&g_stats[5], s5);
    }
}

// ---------------- BN + relu + conv1d(3->1) -> g_q ----------------
__global__ __launch_bounds__(256) void k_q(const float* __restrict__ hT,
                                           const float* __restrict__ rel_emb,
                                           const float* __restrict__ freq,
                                           const void* sidx, const void* ridx,
                                           const float* __restrict__ bng, const float* __restrict__ bnb,
                                           const float* __restrict__ cw,  const float* __restrict__ cb) {
    int idx = blockIdx.x * blockDim.x + threadIdx.x;
    if (idx >= BATCH * HDIM) return;
    int b = idx / HDIM, h = idx % HDIM;
    int is64 = g_is64;
    long long s = ld_idx(sidx, b, is64);
    long long r = ld_idx(ridx, b, is64);
    const float inv = 1.0f / (float)(BATCH * HDIM);
    float m0 = g_stats[0] * inv, m1 = g_stats[2] * inv, m2 = g_stats[4] * inv;
    float v0 = g_stats[1] * inv - m0 * m0;
    float v1 = g_stats[3] * inv - m1 * m1;
    float v2 = g_stats[5] * inv - m2 * m2;
    float rs0 = rsqrtf(v0 + BN_EPS), rs1 = rsqrtf(v1 + BN_EPS), rs2 = rsqrtf(v2 + BN_EPS);
    float x0 = hT[(long long)h * NUM_E + s];
    float x1 = rel_emb[r * HDIM + h];
    float x2 = freq[idx];
    float y0 = fmaxf((x0 - m0) * rs0 * bng[0] + bnb[0], 0.f);
    float y1 = fmaxf((x1 - m1) * rs1 * bng[1] + bnb[1], 0.f);
    float y2 = fmaxf((x2 - m2) * rs2 * bng[2] + bnb[2], 0.f);
    g_q[idx] = y0 * cw[0] + y1 * cw[1] + y2 * cw[2] + cb[0];
}

// ---------------- scores = q @ h_final^T, IN PLACE over hT (panel-exclusive blocks) -----------
// f32x2 packed over k (even/odd partial sums, horizontal add at the end). [R14: improved]
__global__ __launch_bounds__(256, 2) void k_scores(float* __restrict__ out) {
    extern __shared__ float smem[];
    float* h_sm = smem;               // [j=64][202]
    float* q_sm = smem + 64 * 202;    // [bi=64][204]

    const int t = threadIdx.x;
    const long long n0 = (long long)blockIdx.x * 64;
    const int jmax = (NUM_E - n0 >= 64) ? 64 : (int)(NUM_E - n0);

    // stage hT panel transposed into h_sm[j][k] (coalesced reads along n)
    for (int i = t; i < HDIM * 16; i += 256) {
        int c = i / 16, j4 = i % 16;
        float4 v = make_float4(0.f, 0.f, 0.f, 0.f);
        if (j4 * 4 < jmax)
            v = *(const float4*)(out + (long long)c * NUM_E + n0 + j4 * 4);
        h_sm[(j4 * 4 + 0) * 202 + c] = v.x;
        h_sm[(j4 * 4 + 1) * 202 + c] = v.y;
        h_sm[(j4 * 4 + 2) * 202 + c] = v.z;
        h_sm[(j4 * 4 + 3) * 202 + c] = v.w;
    }

    const int tx = t & 15;   // n-lane; cols {tx + 16*ci}
    const int ty = t >> 4;   // b-group of 4

    for (int bc = 0; bc < BATCH / 64; ++bc) {
        const int b0 = bc * 64;
        __syncthreads();     // (first iter: also covers h_sm visibility)
        for (int i = t; i < 64 * 50; i += 256) {
            int bi = i / 50, k4 = i % 50;
            float4 v = *(const float4*)(g_q + (b0 + bi) * HDIM + k4 * 4);
            *(float4*)&q_sm[bi * 204 + k4 * 4] = v;
        }
        __syncthreads();

        unsigned long long acc2[16];
        #pragma unroll
        for (int i = 0; i < 16; i++) acc2[i] = 0ull;

        for (int k4 = 0; k4 < 50; ++k4) {
            ulonglong2 q0 = *(const ulonglong2*)&q_sm[(ty * 4 + 0) * 204 + k4 * 4];
            ulonglong2 q1 = *(const ulonglong2*)&q_sm[(ty * 4 + 1) * 204 + k4 * 4];
            ulonglong2 q2 = *(const ulonglong2*)&q_sm[(ty * 4 + 2) * 204 + k4 * 4];
            ulonglong2 q3 = *(const ulonglong2*)&q_sm[(ty * 4 + 3) * 204 + k4 * 4];
            #pragma unroll
            for (int ci = 0; ci < 4; ++ci) {
                const float* hrow = h_sm + (tx + 16 * ci) * 202 + k4 * 4;
                unsigned long long h01 = *(const unsigned long long*)(hrow);
                unsigned long long h23 = *(const unsigned long long*)(hrow + 2);
                fma2(acc2[0 * 4 + ci], q0.x, h01); fma2(acc2[0 * 4 + ci], q0.y, h23);
                fma2(acc2[1 * 4 + ci], q1.x, h01); fma2(acc2[1 * 4 + ci], q1.y, h23);
                fma2(acc2[2 * 4 + ci], q2.x, h01); fma2(acc2[2 * 4 + ci], q2.y, h23);
                fma2(acc2[3 * 4 + ci], q3.x, h01); fma2(acc2[3 * 4 + ci], q3.y, h23);
            }
        }

        #pragma unroll
        for (int a = 0; a < 4; ++a) {
            long long b = b0 + ty * 4 + a;
            #pragma unroll
            for (int ci = 0; ci < 4; ++ci) {
                long long n = n0 + tx + 16 * ci;
                if (n < NUM_E) {
                    unsigned long long v = acc2[a * 4 + ci];
                    out[b * NUM_E + n] = f2_lo(v) + f2_hi(v);
                }
            }
        }
    }
}

// ---------------- launch ----------------
extern "C" void kernel_launch(void* const* d_in, const int* in_sizes, int n_in,
                              void* d_out, int out_size) {
    const float* ent  = (const float*)d_in[0];
    const float* rel  = (const float*)d_in[1];
    const float* Wn1  = (const float*)d_in[2];
    const float* Wl1  = (const float*)d_in[3];
    const float* Wn2  = (const float*)d_in[4];
    const float* Wl2  = (const float*)d_in[5];
    const float* gth  = (const float*)d_in[6];
    const float* gw   = (const float*)d_in[7];
    const float* gb   = (const float*)d_in[8];
    const float* bng  = (const float*)d_in[9];
    const float* bnb  = (const float*)d_in[10];
    const float* cw   = (const float*)d_in[11];
    const float* cb   = (const float*)d_in[12];
    const float* freq = (const float*)d_in[13];
    const void*  src  = d_in[14];
    const void*  dst  = d_in[15];
    const void*  etp  = d_in[16];
    const void*  sidx = d_in[17];
    const void*  ridx = d_in[18];
    float* out = (float*)d_out;

    float* h1  = out;             // [0, 20M)
    float* agg = out + AGG_OFF;   // [20M, 40M); later h2 in place
    float* hT  = out;             // [0, 20M), transposed h_final (after h1 dead)

    const int TRANS_SMEM  = (32 * 400 + 2 * 8 * 400) * (int)sizeof(float);    // 76.8 KB
    const int SCORES_SMEM = (64 * 202 + 64 * 204) * (int)sizeof(float);       // 103.9 KB
    cudaFuncSetAttribute(k_transform, cudaFuncAttributeMaxDynamicSharedMemorySize, TRANS_SMEM);
    cudaFuncSetAttribute(k_scores,    cudaFuncAttributeMaxDynamicSharedMemorySize, SCORES_SMEM);

    const int zgrid = (NUM_E * H4 + 255) / 256;

    k_zero_init<<<zgrid, 256>>>(agg);
    k_detect<<<1, 32>>>((const unsigned int*)src);

    // layer 1
    k_edges<<<NEDGE / 8, 256>>>(src, dst, etp, rel, ent, agg, 1);
    k_transform<<<NUM_E / 32, 400, TRANS_SMEM>>>(ent, Wn1, Wl1, agg, h1);

    // layer 2 (h2 in place over agg)
    k_zero_agg<<<zgrid, 256>>>(agg);
    k_edges<<<NEDGE / 8, 256>>>(src, dst, etp, rel, h1, agg, 0);
    k_transform<<<NUM_E / 32, 400, TRANS_SMEM>>>(h1, Wn2, Wl2, agg, agg);

    // gate + transposed blend into hT = out[0,20M)
    k_gatepre<<<NUM_E / 8, 256>>>(gth, gw, gb);
    k_blendT<<<NUM_E / 32, 256>>>(agg /*h2*/, ent, hT);

    // ConvE head
    k_bnstats<<<BATCH, 256>>>(hT, rel, freq, sidx, ridx);
    k_q<<<(BATCH * HDIM + 255) / 256, 256>>>(hT, rel, freq, sidx, ridx, bng, bnb, cw, cb);

    // scores in place over the whole output (panel-exclusive blocks)
    k_scores<<<(NUM_E + 63) / 64, 256, SCORES_SMEM>>>(out);
}

// round 16
// speedup vs baseline: 1.1369x; 1.0375x over previous
#include <cuda_runtime.h>
#include <math.h>

#define NUM_E   100000
#define HDIM    200
#define H4      50          // HDIM / 4
#define NEDGE   1000000
#define BATCH   512
#define RRELU_SLOPE 0.2291666666666667f
#define BN_EPS  1e-5f

#define AGG_OFF ((long long)NUM_E * HDIM)   // agg/h2 region starts at out + 20M floats

// ---------------- tiny device globals ONLY (~1.21 MB; no static ctor) ----------------
__device__ float g_deg  [NUM_E];
__device__ float g_gate [NUM_E];
__device__ float g_q    [BATCH * HDIM];
__device__ float g_stats[8];
__device__ int   g_is64;

// ---------------- helpers ----------------
__device__ __forceinline__ long long ld_idx(const void* p, long long i, int is64) {
    if (is64) return ((const long long*)p)[i];
    return (long long)((const int*)p)[i];
}

__device__ __forceinline__ void red_add_v4(float* addr, float4 v) {
    asm volatile("red.global.add.v4.f32 [%0], {%1,%2,%3,%4};"
                 :: "l"(addr), "f"(v.x), "f"(v.y), "f"(v.z), "f"(v.w) : "memory");
}

__device__ __forceinline__ float warp_sum(float v) {
    #pragma unroll
    for (int o = 16; o > 0; o >>= 1) v += __shfl_xor_sync(0xffffffffu, v, o);
    return v;
}

__device__ __forceinline__ float rrelu(float x) {
    return x >= 0.0f ? x : x * RRELU_SLOPE;
}

// packed fp32x2 FMA: d = a*b + d (lanewise on two fp32 in a 64-bit reg)
__device__ __forceinline__ void fma2(unsigned long long& d,
                                     unsigned long long a, unsigned long long b) {
    asm("fma.rn.f32x2 %0, %1, %2, %0;" : "+l"(d) : "l"(a), "l"(b));
}
__device__ __forceinline__ float f2_lo(unsigned long long v) {
    return __uint_as_float((unsigned)(v & 0xffffffffu));
}
__device__ __forceinline__ float f2_hi(unsigned long long v) {
    return __uint_as_float((unsigned)(v >> 32));
}

// ---------------- index width detection (int32 vs int64) ----------------
__global__ __launch_bounds__(32) void k_detect(const unsigned int* w) {
    if (threadIdx.x == 0) {
        int is64 = 1;
        for (int i = 0; i < 64; i++) {
            if (w[2 * i + 1] != 0u) { is64 = 0; break; }
        }
        g_is64 = is64;
    }
}

// ---------------- zero kernels ----------------
__global__ __launch_bounds__(256) void k_zero_init(float* __restrict__ agg) {
    long long i = (long long)blockIdx.x * blockDim.x + threadIdx.x;
    float4 z = make_float4(0.f, 0.f, 0.f, 0.f);
    if (i < (long long)NUM_E * H4) ((float4*)agg)[i] = z;
    if (i < NUM_E / 4)             ((float4*)g_deg)[i] = z;
    if (i < 2)                     ((float4*)g_stats)[i] = z;
}

__global__ __launch_bounds__(256) void k_zero_agg(float* __restrict__ agg) {
    long long i = (long long)blockIdx.x * blockDim.x + threadIdx.x;
    if (i < (long long)NUM_E * H4)
        ((float4*)agg)[i] = make_float4(0.f, 0.f, 0.f, 0.f);
}

// ---------------- edge scatter (warp per edge): agg[dst] += h[src] + rel[etype] ----------------
__global__ __launch_bounds__(256) void k_edges(const void* srcp, const void* dstp, const void* etp,
                                               const float* __restrict__ rel_emb,
                                               const float* __restrict__ hsrc,
                                               float* __restrict__ agg, int do_deg) {
    long long w = ((long long)blockIdx.x * blockDim.x + threadIdx.x) >> 5;
    int lane = threadIdx.x & 31;
    if (w >= NEDGE) return;
    int is64 = g_is64;
    long long d = ld_idx(dstp, w, is64);
    long long t = ld_idx(etp, w, is64);
    long long s = ld_idx(srcp, w, is64);
    if (do_deg && lane == 0) atomicAdd(&g_deg[d], 1.0f);
    const float4* r4 = (const float4*)(rel_emb + t * HDIM);
    const float4* h4 = (const float4*)(hsrc + s * HDIM);
    float* agb = agg + d * HDIM;
    #pragma unroll
    for (int u = 0; u < 2; ++u) {
        int c = lane + u * 32;
        if (c < H4) {
            float4 v = h4[c], r = r4[c];
            v.x += r.x; v.y += r.y; v.z += r.z; v.w += r.w;
            red_add_v4(agb + 4 * c, v);
        }
    }
}

// ---------------- fused node transform (f32x2, 8r x 2c microtile): hout = rrelu(A@Wn + H@Wl)
// Matrix-paired f32x2: acc2[r][c] = {N_partial, L_partial}.
// AH[r][k] = (a*inv, h) pairs, rows of 400 floats (warp-broadcast loads: all lanes share ty).
// W2[k][c] = (wn, wl) pairs, k-row-major rows of 400 floats; load offset 2*tx0 -> conflict-free.
// 8 rows x 2 cols per thread halves W crossbar traffic vs 4x4 (W pair feeds 8 rows).
// 32-row tile, 400 threads (tx0=tid%100 -> cols {tx0, tx0+100}, ty=tid/100 -> 8 rows),
// BK=8 double-buffered, 1 sync/iter. In-place safe over agg (fully staged first).
__global__ __launch_bounds__(400, 2) void k_transform(const float* __restrict__ hin,
                                                      const float* __restrict__ Wn,
                                                      const float* __restrict__ Wl,
                                                      const float* __restrict__ agg,
                                                      float* __restrict__ hout) {
    extern __shared__ float sm[];
    float* AH = sm;                   // [32][400]: 200 (a,h) pairs per row
    float* Wp = AH + 32 * 400;        // [2 buf][8 k][400]: 200 (wn,wl) pairs per k-row

    const int tid = threadIdx.x;
    const int tx0 = tid % 100;        // cols {tx0, tx0+100}
    const int ty  = tid / 100;        // 0..3 -> rows ty*8 .. ty*8+7
    const long long base = (long long)blockIdx.x * 32;

    // stage AH interleaved: (a*inv, h) pairs
    for (int i = tid; i < 32 * H4; i += 400) {
        int r = i / H4, c4 = i % H4;
        long long n = base + r;
        float inv = 1.0f / fmaxf(g_deg[n], 1.0f);
        float4 a = *(const float4*)(agg + n * HDIM + 4 * c4);
        float4 h = *(const float4*)(hin + n * HDIM + 4 * c4);
        *(float4*)(AH + r * 400 + c4 * 8)     = make_float4(a.x * inv, h.x, a.y * inv, h.y);
        *(float4*)(AH + r * 400 + c4 * 8 + 4) = make_float4(a.z * inv, h.z, a.w * inv, h.w);
    }

    // stage W k-tile kt into buffer buf: W2[k][c]=(wn,wl), k-row-major
    auto stageW = [&](int kt, int buf) {
        int k  = tid / 50;            // 0..7
        int c4 = tid % 50;
        float4 wn = *(const float4*)(Wn + (kt * 8 + k) * HDIM + 4 * c4);
        float4 wl = *(const float4*)(Wl + (kt * 8 + k) * HDIM + 4 * c4);
        float* Wb = Wp + buf * 3200 + k * 400 + 8 * c4;
        *(float4*)(Wb)     = make_float4(wn.x, wl.x, wn.y, wl.y);
        *(float4*)(Wb + 4) = make_float4(wn.z, wl.z, wn.w, wl.w);
    };

    stageW(0, 0);
    __syncthreads();

    unsigned long long acc2[16];      // [r 0..7][ci 0..1]
    #pragma unroll
    for (int i = 0; i < 16; i++) acc2[i] = 0ull;

    for (int kt = 0; kt < 25; ++kt) {
        const int cur = kt & 1;
        if (kt < 24) stageW(kt + 1, cur ^ 1);   // overlaps with compute below

        const float* Wc = Wp + cur * 3200;

        #pragma unroll
        for (int g = 0; g < 4; ++g) {           // 2 k-values per g
            // W pairs for k = kt*8+2g, +1 at both cols (conflict-free LDS.64)
            unsigned long long w00 = *(const unsigned long long*)(Wc + (g * 2 + 0) * 400 + 2 * tx0);
            unsigned long long w01 = *(const unsigned long long*)(Wc + (g * 2 + 1) * 400 + 2 * tx0);
            unsigned long long w10 = *(const unsigned long long*)(Wc + (g * 2 + 0) * 400 + 2 * tx0 + 200);
            unsigned long long w11 = *(const unsigned long long*)(Wc + (g * 2 + 1) * 400 + 2 * tx0 + 200);
            #pragma unroll
            for (int half = 0; half < 2; ++half) {
                const int rb = ty * 8 + half * 4;
                ulonglong2 ah0 = *(const ulonglong2*)(AH + (rb + 0) * 400 + kt * 16 + g * 4);
                ulonglong2 ah1 = *(const ulonglong2*)(AH + (rb + 1) * 400 + kt * 16 + g * 4);
                ulonglong2 ah2 = *(const ulonglong2*)(AH + (rb + 2) * 400 + kt * 16 + g * 4);
                ulonglong2 ah3 = *(const ulonglong2*)(AH + (rb + 3) * 400 + kt * 16 + g * 4);
                const int a0 = (half * 4) * 2;
                fma2(acc2[a0 + 0], ah0.x, w00); fma2(acc2[a0 + 0], ah0.y, w01);
                fma2(acc2[a0 + 1], ah0.x, w10); fma2(acc2[a0 + 1], ah0.y, w11);
                fma2(acc2[a0 + 2], ah1.x, w00); fma2(acc2[a0 + 2], ah1.y, w01);
                fma2(acc2[a0 + 3], ah1.x, w10); fma2(acc2[a0 + 3], ah1.y, w11);
                fma2(acc2[a0 + 4], ah2.x, w00); fma2(acc2[a0 + 4], ah2.y, w01);
                fma2(acc2[a0 + 5], ah2.x, w10); fma2(acc2[a0 + 5], ah2.y, w11);
                fma2(acc2[a0 + 6], ah3.x, w00); fma2(acc2[a0 + 6], ah3.y, w01);
                fma2(acc2[a0 + 7], ah3.x, w10); fma2(acc2[a0 + 7], ah3.y, w11);
            }
        }
        __syncthreads();
    }

    #pragma unroll
    for (int rr = 0; rr < 8; ++rr) {
        long long n = base + ty * 8 + rr;
        unsigned long long v0 = acc2[rr * 2 + 0];
        unsigned long long v1 = acc2[rr * 2 + 1];
        hout[n * HDIM + tx0]       = rrelu(f2_lo(v0) + f2_hi(v0));
        hout[n * HDIM + tx0 + 100] = rrelu(f2_lo(v1) + f2_hi(v1));
    }
}

// ---------------- gate scalar per node ----------------
__global__ __launch_bounds__(256) void k_gatepre(const float* __restrict__ theta,
                                                 const float* __restrict__ gw,
                                                 const float* __restrict__ gb) {
    long long w = ((long long)blockIdx.x * blockDim.x + threadIdx.x) >> 5;
    int lane = threadIdx.x & 31;
    if (w >= NUM_E) return;
    const float4* t4 = (const float4*)(theta + w * HDIM);
    const float4* w4 = (const float4*)gw;
    float p = 0.f;
    #pragma unroll
    for (int u = 0; u < 2; ++u) {
        int c = lane + u * 32;
        if (c < H4) {
            float4 a = t4[c], b = w4[c];
            p += a.x * b.x + a.y * b.y + a.z * b.z + a.w * b.w;
        }
    }
    p = warp_sum(p);
    if (lane == 0) g_gate[w] = 1.0f / (1.0f + expf(-(p + gb[0])));
}

// ---------------- blend + transpose: hT[c][n] ----------------
__global__ __launch_bounds__(256) void k_blendT(const float* __restrict__ h2,
                                                const float* __restrict__ ent,
                                                float* __restrict__ hT) {
    __shared__ float sm[32 * 201];
    const int tid = threadIdx.x;
    const long long n0 = (long long)blockIdx.x * 32;

    for (int i = tid; i < 32 * H4; i += 256) {
        int r = i / H4, c4 = i % H4;
        long long n = n0 + r;
        float g = g_gate[n], og = 1.0f - g;
        float4 h = *(const float4*)(h2 + n * HDIM + 4 * c4);
        float4 e = *(const float4*)(ent + n * HDIM + 4 * c4);
        sm[r * 201 + 4 * c4 + 0] = g * h.x + og * e.x;
        sm[r * 201 + 4 * c4 + 1] = g * h.y + og * e.y;
        sm[r * 201 + 4 * c4 + 2] = g * h.z + og * e.z;
        sm[r * 201 + 4 * c4 + 3] = g * h.w + og * e.w;
    }
    __syncthreads();

    for (int i = tid; i < HDIM * 32; i += 256) {
        int r = i & 31;
        int c = i >> 5;
        hT[(long long)c * NUM_E + n0 + r] = sm[r * 201 + c];
    }
}

// ---------------- BN batch statistics ----------------
__global__ __launch_bounds__(256) void k_bnstats(const float* __restrict__ hT,
                                                 const float* __restrict__ rel_emb,
                                                 const float* __restrict__ freq,
                                                 const void* sidx, const void* ridx) {
    int b = blockIdx.x;
    int tid = threadIdx.x;
    int lane = tid & 31;
    int is64 = g_is64;
    long long s = ld_idx(sidx, b, is64);
    long long r = ld_idx(ridx, b, is64);
    float e = 0.f, rr = 0.f, f = 0.f;
    if (tid < HDIM) {
        e  = hT[(long long)tid * NUM_E + s];
        rr = rel_emb[r * HDIM + tid];
        f  = freq[(long long)b * HDIM + tid];
    }
    float s0 = warp_sum(e),  s1 = warp_sum(e * e);
    float s2 = warp_sum(rr), s3 = warp_sum(rr * rr);
    float s4 = warp_sum(f),  s5 = warp_sum(f * f);
    if (lane == 0) {
        atomicAdd(&g_stats[0], s0); atomicAdd(&g_stats[1], s1);
        atomicAdd(&g_stats[2], s2); atomicAdd(&g_stats[3], s3);
        atomicAdd(&g_stats[4], s4); atomicAdd(&g_stats[5], s5);
    }
}

// ---------------- BN + relu + conv1d(3->1) -> g_q ----------------
__global__ __launch_bounds__(256) void k_q(const float* __restrict__ hT,
                                           const float* __restrict__ rel_emb,
                                           const float* __restrict__ freq,
                                           const void* sidx, const void* ridx,
                                           const float* __restrict__ bng, const float* __restrict__ bnb,
                                           const float* __restrict__ cw,  const float* __restrict__ cb) {
    int idx = blockIdx.x * blockDim.x + threadIdx.x;
    if (idx >= BATCH * HDIM) return;
    int b = idx / HDIM, h = idx % HDIM;
    int is64 = g_is64;
    long long s = ld_idx(sidx, b, is64);
    long long r = ld_idx(ridx, b, is64);
    const float inv = 1.0f / (float)(BATCH * HDIM);
    float m0 = g_stats[0] * inv, m1 = g_stats[2] * inv, m2 = g_stats[4] * inv;
    float v0 = g_stats[1] * inv - m0 * m0;
    float v1 = g_stats[3] * inv - m1 * m1;
    float v2 = g_stats[5] * inv - m2 * m2;
    float rs0 = rsqrtf(v0 + BN_EPS), rs1 = rsqrtf(v1 + BN_EPS), rs2 = rsqrtf(v2 + BN_EPS);
    float x0 = hT[(long long)h * NUM_E + s];
    float x1 = rel_emb[r * HDIM + h];
    float x2 = freq[idx];
    float y0 = fmaxf((x0 - m0) * rs0 * bng[0] + bnb[0], 0.f);
    float y1 = fmaxf((x1 - m1) * rs1 * bng[1] + bnb[1], 0.f);
    float y2 = fmaxf((x2 - m2) * rs2 * bng[2] + bnb[2], 0.f);
    g_q[idx] = y0 * cw[0] + y1 * cw[1] + y2 * cw[2] + cb[0];
}

// ---------------- scores = q @ h_final^T, IN PLACE over hT (panel-exclusive blocks) -----------
// f32x2 packed over k (even/odd partial sums, horizontal add at the end). [R15-proven]
__global__ __launch_bounds__(256, 2) void k_scores(float* __restrict__ out) {
    extern __shared__ float smem[];
    float* h_sm = smem;               // [j=64][202]
    float* q_sm = smem + 64 * 202;    // [bi=64][204]

    const int t = threadIdx.x;
    const long long n0 = (long long)blockIdx.x * 64;
    const int jmax = (NUM_E - n0 >= 64) ? 64 : (int)(NUM_E - n0);

    // stage hT panel transposed into h_sm[j][k] (coalesced reads along n)
    for (int i = t; i < HDIM * 16; i += 256) {
        int c = i / 16, j4 = i % 16;
        float4 v = make_float4(0.f, 0.f, 0.f, 0.f);
        if (j4 * 4 < jmax)
            v = *(const float4*)(out + (long long)c * NUM_E + n0 + j4 * 4);
        h_sm[(j4 * 4 + 0) * 202 + c] = v.x;
        h_sm[(j4 * 4 + 1) * 202 + c] = v.y;
        h_sm[(j4 * 4 + 2) * 202 + c] = v.z;
        h_sm[(j4 * 4 + 3) * 202 + c] = v.w;
    }

    const int tx = t & 15;   // n-lane; cols {tx + 16*ci}
    const int ty = t >> 4;   // b-group of 4

    for (int bc = 0; bc < BATCH / 64; ++bc) {
        const int b0 = bc * 64;
        __syncthreads();     // (first iter: also covers h_sm visibility)
        for (int i = t; i < 64 * 50; i += 256) {
            int bi = i / 50, k4 = i % 50;
            float4 v = *(const float4*)(g_q + (b0 + bi) * HDIM + k4 * 4);
            *(float4*)&q_sm[bi * 204 + k4 * 4] = v;
        }
        __syncthreads();

        unsigned long long acc2[16];
        #pragma unroll
        for (int i = 0; i < 16; i++) acc2[i] = 0ull;

        for (int k4 = 0; k4 < 50; ++k4) {
            ulonglong2 q0 = *(const ulonglong2*)&q_sm[(ty * 4 + 0) * 204 + k4 * 4];
            ulonglong2 q1 = *(const ulonglong2*)&q_sm[(ty * 4 + 1) * 204 + k4 * 4];
            ulonglong2 q2 = *(const ulonglong2*)&q_sm[(ty * 4 + 2) * 204 + k4 * 4];
            ulonglong2 q3 = *(const ulonglong2*)&q_sm[(ty * 4 + 3) * 204 + k4 * 4];
            #pragma unroll
            for (int ci = 0; ci < 4; ++ci) {
                const float* hrow = h_sm + (tx + 16 * ci) * 202 + k4 * 4;
                unsigned long long h01 = *(const unsigned long long*)(hrow);
                unsigned long long h23 = *(const unsigned long long*)(hrow + 2);
                fma2(acc2[0 * 4 + ci], q0.x, h01); fma2(acc2[0 * 4 + ci], q0.y, h23);
                fma2(acc2[1 * 4 + ci], q1.x, h01); fma2(acc2[1 * 4 + ci], q1.y, h23);
                fma2(acc2[2 * 4 + ci], q2.x, h01); fma2(acc2[2 * 4 + ci], q2.y, h23);
                fma2(acc2[3 * 4 + ci], q3.x, h01); fma2(acc2[3 * 4 + ci], q3.y, h23);
            }
        }

        #pragma unroll
        for (int a = 0; a < 4; ++a) {
            long long b = b0 + ty * 4 + a;
            #pragma unroll
            for (int ci = 0; ci < 4; ++ci) {
                long long n = n0 + tx + 16 * ci;
                if (n < NUM_E) {
                    unsigned long long v = acc2[a * 4 + ci];
                    out[b * NUM_E + n] = f2_lo(v) + f2_hi(v);
                }
            }
        }
    }
}

// ---------------- launch ----------------
extern "C" void kernel_launch(void* const* d_in, const int* in_sizes, int n_in,
                              void* d_out, int out_size) {
    const float* ent  = (const float*)d_in[0];
    const float* rel  = (const float*)d_in[1];
    const float* Wn1  = (const float*)d_in[2];
    const float* Wl1  = (const float*)d_in[3];
    const float* Wn2  = (const float*)d_in[4];
    const float* Wl2  = (const float*)d_in[5];
    const float* gth  = (const float*)d_in[6];
    const float* gw   = (const float*)d_in[7];
    const float* gb   = (const float*)d_in[8];
    const float* bng  = (const float*)d_in[9];
    const float* bnb  = (const float*)d_in[10];
    const float* cw   = (const float*)d_in[11];
    const float* cb   = (const float*)d_in[12];
    const float* freq = (const float*)d_in[13];
    const void*  src  = d_in[14];
    const void*  dst  = d_in[15];
    const void*  etp  = d_in[16];
    const void*  sidx = d_in[17];
    const void*  ridx = d_in[18];
    float* out = (float*)d_out;

    float* h1  = out;             // [0, 20M)
    float* agg = out + AGG_OFF;   // [20M, 40M); later h2 in place
    float* hT  = out;             // [0, 20M), transposed h_final (after h1 dead)

    const int TRANS_SMEM  = (32 * 400 + 2 * 8 * 400) * (int)sizeof(float);    // 76.8 KB
    const int SCORES_SMEM = (64 * 202 + 64 * 204) * (int)sizeof(float);       // 103.9 KB
    cudaFuncSetAttribute(k_transform, cudaFuncAttributeMaxDynamicSharedMemorySize, TRANS_SMEM);
    cudaFuncSetAttribute(k_scores,    cudaFuncAttributeMaxDynamicSharedMemorySize, SCORES_SMEM);

    const int zgrid = (NUM_E * H4 + 255) / 256;

    k_zero_init<<<zgrid, 256>>>(agg);
    k_detect<<<1, 32>>>((const unsigned int*)src);

    // layer 1
    k_edges<<<NEDGE / 8, 256>>>(src, dst, etp, rel, ent, agg, 1);
    k_transform<<<NUM_E / 32, 400, TRANS_SMEM>>>(ent, Wn1, Wl1, agg, h1);

    // layer 2 (h2 in place over agg)
    k_zero_agg<<<zgrid, 256>>>(agg);
    k_edges<<<NEDGE / 8, 256>>>(src, dst, etp, rel, h1, agg, 0);
    k_transform<<<NUM_E / 32, 400, TRANS_SMEM>>>(h1, Wn2, Wl2, agg, agg);

    // gate + transposed blend into hT = out[0,20M)
    k_gatepre<<<NUM_E / 8, 256>>>(gth, gw, gb);
    k_blendT<<<NUM_E / 32, 256>>>(agg /*h2*/, ent, hT);

    // ConvE head
    k_bnstats<<<BATCH, 256>>>(hT, rel, freq, sidx, ridx);
    k_q<<<(BATCH * HDIM + 255) / 256, 256>>>(hT, rel, freq, sidx, ridx, bng, bnb, cw, cb);

    // scores in place over the whole output (panel-exclusive blocks)
    k_scores<<<(NUM_E + 63) / 64, 256, SCORES_SMEM>>>(out);
}

// round 17
// speedup vs baseline: 1.1379x; 1.0009x over previous
#include <cuda_runtime.h>
#include <math.h>

#define NUM_E   100000
#define HDIM    200
#define H4      50          // HDIM / 4
#define NEDGE   1000000
#define BATCH   512
#define RRELU_SLOPE 0.2291666666666667f
#define BN_EPS  1e-5f

#define AGG_OFF ((long long)NUM_E * HDIM)   // agg/h2 region starts at out + 20M floats

// ---------------- tiny device globals ONLY (~0.8 MB; no static ctor) ----------------
__device__ float g_deg  [NUM_E];
__device__ float g_q    [BATCH * HDIM];
__device__ float g_stats[8];
__device__ int   g_is64;

// ---------------- helpers ----------------
__device__ __forceinline__ long long ld_idx(const void* p, long long i, int is64) {
    if (is64) return ((const long long*)p)[i];
    return (long long)((const int*)p)[i];
}

__device__ __forceinline__ void red_add_v4(float* addr, float4 v) {
    asm volatile("red.global.add.v4.f32 [%0], {%1,%2,%3,%4};"
                 :: "l"(addr), "f"(v.x), "f"(v.y), "f"(v.z), "f"(v.w) : "memory");
}

__device__ __forceinline__ float warp_sum(float v) {
    #pragma unroll
    for (int o = 16; o > 0; o >>= 1) v += __shfl_xor_sync(0xffffffffu, v, o);
    return v;
}

__device__ __forceinline__ float rrelu(float x) {
    return x >= 0.0f ? x : x * RRELU_SLOPE;
}

// packed fp32x2 FMA: d = a*b + d (lanewise on two fp32 in a 64-bit reg)
__device__ __forceinline__ void fma2(unsigned long long& d,
                                     unsigned long long a, unsigned long long b) {
    asm("fma.rn.f32x2 %0, %1, %2, %0;" : "+l"(d) : "l"(a), "l"(b));
}
__device__ __forceinline__ float f2_lo(unsigned long long v) {
    return __uint_as_float((unsigned)(v & 0xffffffffu));
}
__device__ __forceinline__ float f2_hi(unsigned long long v) {
    return __uint_as_float((unsigned)(v >> 32));
}

// ---------------- index width detection (int32 vs int64) ----------------
__global__ __launch_bounds__(32) void k_detect(const unsigned int* w) {
    if (threadIdx.x == 0) {
        int is64 = 1;
        for (int i = 0; i < 64; i++) {
            if (w[2 * i + 1] != 0u) { is64 = 0; break; }
        }
        g_is64 = is64;
    }
}

// ---------------- zero kernels ----------------
__global__ __launch_bounds__(256) void k_zero_init(float* __restrict__ agg) {
    long long i = (long long)blockIdx.x * blockDim.x + threadIdx.x;
    float4 z = make_float4(0.f, 0.f, 0.f, 0.f);
    if (i < (long long)NUM_E * H4) ((float4*)agg)[i] = z;
    if (i < NUM_E / 4)             ((float4*)g_deg)[i] = z;
    if (i < 2)                     ((float4*)g_stats)[i] = z;
}

__global__ __launch_bounds__(256) void k_zero_agg(float* __restrict__ agg) {
    long long i = (long long)blockIdx.x * blockDim.x + threadIdx.x;
    if (i < (long long)NUM_E * H4)
        ((float4*)agg)[i] = make_float4(0.f, 0.f, 0.f, 0.f);
}

// ---------------- edge scatter (warp per edge): agg[dst] += h[src] + rel[etype] ----------------
__global__ __launch_bounds__(256) void k_edges(const void* srcp, const void* dstp, const void* etp,
                                               const float* __restrict__ rel_emb,
                                               const float* __restrict__ hsrc,
                                               float* __restrict__ agg, int do_deg) {
    long long w = ((long long)blockIdx.x * blockDim.x + threadIdx.x) >> 5;
    int lane = threadIdx.x & 31;
    if (w >= NEDGE) return;
    int is64 = g_is64;
    long long d = ld_idx(dstp, w, is64);
    long long t = ld_idx(etp, w, is64);
    long long s = ld_idx(srcp, w, is64);
    if (do_deg && lane == 0) atomicAdd(&g_deg[d], 1.0f);
    const float4* r4 = (const float4*)(rel_emb + t * HDIM);
    const float4* h4 = (const float4*)(hsrc + s * HDIM);
    float* agb = agg + d * HDIM;
    #pragma unroll
    for (int u = 0; u < 2; ++u) {
        int c = lane + u * 32;
        if (c < H4) {
            float4 v = h4[c], r = r4[c];
            v.x += r.x; v.y += r.y; v.z += r.z; v.w += r.w;
            red_add_v4(agb + 4 * c, v);
        }
    }
}

// ---------------- fused node transform (f32x2, 8r x 2c, col+k-paired W): hout = rrelu(A@Wn+H@Wl)
// AH[r][k] = (a*inv, h) pairs, rows of 400 floats (warp-broadcast loads).
// W[g][c] = (wn_k0, wl_k0, wn_k1, wl_k1) 16B entries (k0=2g even, k1 odd), row = 200 entries.
//   Inner load: 2 independent LDS.128 per g at word 4*tx0 (contiguous 512B/warp, conflict-free).
// 32-row tile, 400 threads (tx0=tid%100 -> cols {tx0,tx0+100}, ty=tid/100 -> 8 rows),
// BK=8 double-buffered W, 1 sync/iter. In-place safe over agg (fully staged first).
__global__ __launch_bounds__(400, 2) void k_transform(const float* __restrict__ hin,
                                                      const float* __restrict__ Wn,
                                                      const float* __restrict__ Wl,
                                                      const float* __restrict__ agg,
                                                      float* __restrict__ hout) {
    extern __shared__ float sm[];
    float* AH = sm;                   // [32][400]: 200 (a,h) pairs per row
    float* Wp = AH + 32 * 400;        // [2 buf][4 g][800]: 200 16B entries per g-row

    const int tid = threadIdx.x;
    const int tx0 = tid % 100;        // cols {tx0, tx0+100}
    const int ty  = tid / 100;        // 0..3 -> rows ty*8 .. ty*8+7
    const long long base = (long long)blockIdx.x * 32;

    // stage AH interleaved: (a*inv, h) pairs
    for (int i = tid; i < 32 * H4; i += 400) {
        int r = i / H4, c4 = i % H4;
        long long n = base + r;
        float inv = 1.0f / fmaxf(g_deg[n], 1.0f);
        float4 a = *(const float4*)(agg + n * HDIM + 4 * c4);
        float4 h = *(const float4*)(hin + n * HDIM + 4 * c4);
        *(float4*)(AH + r * 400 + c4 * 8)     = make_float4(a.x * inv, h.x, a.y * inv, h.y);
        *(float4*)(AH + r * 400 + c4 * 8 + 4) = make_float4(a.z * inv, h.z, a.w * inv, h.w);
    }

    // stage W k-tile kt into buffer buf: entry (g,c) = (wn[2g][c], wl[2g][c], wn[2g+1][c], wl[2g+1][c])
    // 800 entries, 2 per thread; lane-contiguous STS.128, coalesced scalar LDG gathers.
    auto stageW = [&](int kt, int buf) {
        float* Wb = Wp + buf * 3200;
        #pragma unroll
        for (int u = 0; u < 2; ++u) {
            int e = tid + u * 400;        // 0..799
            int g = e / 200, c = e % 200;
            int k0 = (kt * 8 + 2 * g) * HDIM + c;
            int k1 = k0 + HDIM;
            *(float4*)(Wb + g * 800 + 4 * c) =
                make_float4(Wn[k0], Wl[k0], Wn[k1], Wl[k1]);
        }
    };

    stageW(0, 0);
    __syncthreads();

    unsigned long long acc2[16];      // [r 0..7][ci 0..1]
    #pragma unroll
    for (int i = 0; i < 16; i++) acc2[i] = 0ull;

    for (int kt = 0; kt < 25; ++kt) {
        const int cur = kt & 1;
        if (kt < 24) stageW(kt + 1, cur ^ 1);   // overlaps with compute below

        const float* Wc = Wp + cur * 3200;

        #pragma unroll
        for (int g = 0; g < 4; ++g) {           // 2 k-values per g
            ulonglong2 wa = *(const ulonglong2*)(Wc + g * 800 + 4 * tx0);         // col tx0: (w00,w01)
            ulonglong2 wb = *(const ulonglong2*)(Wc + g * 800 + 4 * tx0 + 400);   // col tx0+100: (w10,w11)
            const unsigned long long w00 = wa.x, w01 = wa.y;
            const unsigned long long w10 = wb.x, w11 = wb.y;
            #pragma unroll
            for (int half = 0; half < 2; ++half) {
                const int rb = ty * 8 + half * 4;
                ulonglong2 ah0 = *(const ulonglong2*)(AH + (rb + 0) * 400 + kt * 16 + g * 4);
                ulonglong2 ah1 = *(const ulonglong2*)(AH + (rb + 1) * 400 + kt * 16 + g * 4);
                ulonglong2 ah2 = *(const ulonglong2*)(AH + (rb + 2) * 400 + kt * 16 + g * 4);
                ulonglong2 ah3 = *(const ulonglong2*)(AH + (rb + 3) * 400 + kt * 16 + g * 4);
                const int a0 = (half * 4) * 2;
                fma2(acc2[a0 + 0], ah0.x, w00); fma2(acc2[a0 + 0], ah0.y, w01);
                fma2(acc2[a0 + 1], ah0.x, w10); fma2(acc2[a0 + 1], ah0.y, w11);
                fma2(acc2[a0 + 2], ah1.x, w00); fma2(acc2[a0 + 2], ah1.y, w01);
                fma2(acc2[a0 + 3], ah1.x, w10); fma2(acc2[a0 + 3], ah1.y, w11);
                fma2(acc2[a0 + 4], ah2.x, w00); fma2(acc2[a0 + 4], ah2.y, w01);
                fma2(acc2[a0 + 5], ah2.x, w10); fma2(acc2[a0 + 5], ah2.y, w11);
                fma2(acc2[a0 + 6], ah3.x, w00); fma2(acc2[a0 + 6], ah3.y, w01);
                fma2(acc2[a0 + 7], ah3.x, w10); fma2(acc2[a0 + 7], ah3.y, w11);
            }
        }
        __syncthreads();
    }

    #pragma unroll
    for (int rr = 0; rr < 8; ++rr) {
        long long n = base + ty * 8 + rr;
        unsigned long long v0 = acc2[rr * 2 + 0];
        unsigned long long v1 = acc2[rr * 2 + 1];
        hout[n * HDIM + tx0]       = rrelu(f2_lo(v0) + f2_hi(v0));
        hout[n * HDIM + tx0 + 100] = rrelu(f2_lo(v1) + f2_hi(v1));
    }
}

// ---------------- fused gate + blend + transpose: hT[c][n] = g*h2 + (1-g)*ent ----------------
// 8 warps x 4 nodes compute sigmoid gates into smem, then blend + transposed store.
__global__ __launch_bounds__(256) void k_blendT(const float* __restrict__ h2,
                                                const float* __restrict__ ent,
                                                const float* __restrict__ theta,
                                                const float* __restrict__ gw,
                                                const float* __restrict__ gb,
                                                float* __restrict__ hT) {
    __shared__ float sm[32 * 201];
    __shared__ float sg[32];
    const int tid = threadIdx.x;
    const int wid = tid >> 5, lane = tid & 31;
    const long long n0 = (long long)blockIdx.x * 32;

    // gates
    #pragma unroll
    for (int j = 0; j < 4; ++j) {
        int r = wid * 4 + j;
        long long n = n0 + r;
        const float4* t4 = (const float4*)(theta + n * HDIM);
        const float4* w4 = (const float4*)gw;
        float p = 0.f;
        #pragma unroll
        for (int u = 0; u < 2; ++u) {
            int c = lane + u * 32;
            if (c < H4) {
                float4 a = t4[c], b = w4[c];
                p += a.x * b.x + a.y * b.y + a.z * b.z + a.w * b.w;
            }
        }
        p = warp_sum(p);
        if (lane == 0) sg[r] = 1.0f / (1.0f + expf(-(p + gb[0])));
    }
    __syncthreads();

    for (int i = tid; i < 32 * H4; i += 256) {
        int r = i / H4, c4 = i % H4;
        long long n = n0 + r;
        float g = sg[r], og = 1.0f - g;
        float4 h = *(const float4*)(h2 + n * HDIM + 4 * c4);
        float4 e = *(const float4*)(ent + n * HDIM + 4 * c4);
        sm[r * 201 + 4 * c4 + 0] = g * h.x + og * e.x;
        sm[r * 201 + 4 * c4 + 1] = g * h.y + og * e.y;
        sm[r * 201 + 4 * c4 + 2] = g * h.z + og * e.z;
        sm[r * 201 + 4 * c4 + 3] = g * h.w + og * e.w;
    }
    __syncthreads();

    for (int i = tid; i < HDIM * 32; i += 256) {
        int r = i & 31;
        int c = i >> 5;
        hT[(long long)c * NUM_E + n0 + r] = sm[r * 201 + c];
    }
}

// ---------------- BN batch statistics ----------------
__global__ __launch_bounds__(256) void k_bnstats(const float* __restrict__ hT,
                                                 const float* __restrict__ rel_emb,
                                                 const float* __restrict__ freq,
                                                 const void* sidx, const void* ridx) {
    int b = blockIdx.x;
    int tid = threadIdx.x;
    int lane = tid & 31;
    int is64 = g_is64;
    long long s = ld_idx(sidx, b, is64);
    long long r = ld_idx(ridx, b, is64);
    float e = 0.f, rr = 0.f, f = 0.f;
    if (tid < HDIM) {
        e  = hT[(long long)tid * NUM_E + s];
        rr = rel_emb[r * HDIM + tid];
        f  = freq[(long long)b * HDIM + tid];
    }
    float s0 = warp_sum(e),  s1 = warp_sum(e * e);
    float s2 = warp_sum(rr), s3 = warp_sum(rr * rr);
    float s4 = warp_sum(f),  s5 = warp_sum(f * f);
    if (lane == 0) {
        atomicAdd(&g_stats[0], s0); atomicAdd(&g_stats[1], s1);
        atomicAdd(&g_stats[2], s2); atomicAdd(&g_stats[3], s3);
        atomicAdd(&g_stats[4], s4); atomicAdd(&g_stats[5], s5);
    }
}

// ---------------- BN + relu + conv1d(3->1) -> g_q ----------------
__global__ __launch_bounds__(256) void k_q(const float* __restrict__ hT,
                                           const float* __restrict__ rel_emb,
                                           const float* __restrict__ freq,
                                           const void* sidx, const void* ridx,
                                           const float* __restrict__ bng, const float* __restrict__ bnb,
                                           const float* __restrict__ cw,  const float* __restrict__ cb) {
    int idx = blockIdx.x * blockDim.x + threadIdx.x;
    if (idx >= BATCH * HDIM) return;
    int b = idx / HDIM, h = idx % HDIM;
    int is64 = g_is64;
    long long s = ld_idx(sidx, b, is64);
    long long r = ld_idx(ridx, b, is64);
    const float inv = 1.0f / (float)(BATCH * HDIM);
    float m0 = g_stats[0] * inv, m1 = g_stats[2] * inv, m2 = g_stats[4] * inv;
    float v0 = g_stats[1] * inv - m0 * m0;
    float v1 = g_stats[3] * inv - m1 * m1;
    float v2 = g_stats[5] * inv - m2 * m2;
    float rs0 = rsqrtf(v0 + BN_EPS), rs1 = rsqrtf(v1 + BN_EPS), rs2 = rsqrtf(v2 + BN_EPS);
    float x0 = hT[(long long)h * NUM_E + s];
    float x1 = rel_emb[r * HDIM + h];
    float x2 = freq[idx];
    float y0 = fmaxf((x0 - m0) * rs0 * bng[0] + bnb[0], 0.f);
    float y1 = fmaxf((x1 - m1) * rs1 * bng[1] + bnb[1], 0.f);
    float y2 = fmaxf((x2 - m2) * rs2 * bng[2] + bnb[2], 0.f);
    g_q[idx] = y0 * cw[0] + y1 * cw[1] + y2 * cw[2] + cb[0];
}

// ---------------- scores = q @ h_final^T, IN PLACE over hT (panel-exclusive blocks) -----------
// f32x2 packed over k (even/odd partial sums, horizontal add at the end). [R15/16-proven]
__global__ __launch_bounds__(256, 2) void k_scores(float* __restrict__ out) {
    extern __shared__ float smem[];
    float* h_sm = smem;               // [j=64][202]
    float* q_sm = smem + 64 * 202;    // [bi=64][204]

    const int t = threadIdx.x;
    const long long n0 = (long long)blockIdx.x * 64;
    const int jmax = (NUM_E - n0 >= 64) ? 64 : (int)(NUM_E - n0);

    // stage hT panel transposed into h_sm[j][k] (coalesced reads along n)
    for (int i = t; i < HDIM * 16; i += 256) {
        int c = i / 16, j4 = i % 16;
        float4 v = make_float4(0.f, 0.f, 0.f, 0.f);
        if (j4 * 4 < jmax)
            v = *(const float4*)(out + (long long)c * NUM_E + n0 + j4 * 4);
        h_sm[(j4 * 4 + 0) * 202 + c] = v.x;
        h_sm[(j4 * 4 + 1) * 202 + c] = v.y;
        h_sm[(j4 * 4 + 2) * 202 + c] = v.z;
        h_sm[(j4 * 4 + 3) * 202 + c] = v.w;
    }

    const int tx = t & 15;   // n-lane; cols {tx + 16*ci}
    const int ty = t >> 4;   // b-group of 4

    for (int bc = 0; bc < BATCH / 64; ++bc) {
        const int b0 = bc * 64;
        __syncthreads();     // (first iter: also covers h_sm visibility)
        for (int i = t; i < 64 * 50; i += 256) {
            int bi = i / 50, k4 = i % 50;
            float4 v = *(const float4*)(g_q + (b0 + bi) * HDIM + k4 * 4);
            *(float4*)&q_sm[bi * 204 + k4 * 4] = v;
        }
        __syncthreads();

        unsigned long long acc2[16];
        #pragma unroll
        for (int i = 0; i < 16; i++) acc2[i] = 0ull;

        for (int k4 = 0; k4 < 50; ++k4) {
            ulonglong2 q0 = *(const ulonglong2*)&q_sm[(ty * 4 + 0) * 204 + k4 * 4];
            ulonglong2 q1 = *(const ulonglong2*)&q_sm[(ty * 4 + 1) * 204 + k4 * 4];
            ulonglong2 q2 = *(const ulonglong2*)&q_sm[(ty * 4 + 2) * 204 + k4 * 4];
            ulonglong2 q3 = *(const ulonglong2*)&q_sm[(ty * 4 + 3) * 204 + k4 * 4];
            #pragma unroll
            for (int ci = 0; ci < 4; ++ci) {
                const float* hrow = h_sm + (tx + 16 * ci) * 202 + k4 * 4;
                unsigned long long h01 = *(const unsigned long long*)(hrow);
                unsigned long long h23 = *(const unsigned long long*)(hrow + 2);
                fma2(acc2[0 * 4 + ci], q0.x, h01); fma2(acc2[0 * 4 + ci], q0.y, h23);
                fma2(acc2[1 * 4 + ci], q1.x, h01); fma2(acc2[1 * 4 + ci], q1.y, h23);
                fma2(acc2[2 * 4 + ci], q2.x, h01); fma2(acc2[2 * 4 + ci], q2.y, h23);
                fma2(acc2[3 * 4 + ci], q3.x, h01); fma2(acc2[3 * 4 + ci], q3.y, h23);
            }
        }

        #pragma unroll
        for (int a = 0; a < 4; ++a) {
            long long b = b0 + ty * 4 + a;
            #pragma unroll
            for (int ci = 0; ci < 4; ++ci) {
                long long n = n0 + tx + 16 * ci;
                if (n < NUM_E) {
                    unsigned long long v = acc2[a * 4 + ci];
                    out[b * NUM_E + n] = f2_lo(v) + f2_hi(v);
                }
            }
        }
    }
}

// ---------------- launch ----------------
extern "C" void kernel_launch(void* const* d_in, const int* in_sizes, int n_in,
                              void* d_out, int out_size) {
    const float* ent  = (const float*)d_in[0];
    const float* rel  = (const float*)d_in[1];
    const float* Wn1  = (const float*)d_in[2];
    const float* Wl1  = (const float*)d_in[3];
    const float* Wn2  = (const float*)d_in[4];
    const float* Wl2  = (const float*)d_in[5];
    const float* gth  = (const float*)d_in[6];
    const float* gw   = (const float*)d_in[7];
    const float* gb   = (const float*)d_in[8];
    const float* bng  = (const float*)d_in[9];
    const float* bnb  = (const float*)d_in[10];
    const float* cw   = (const float*)d_in[11];
    const float* cb   = (const float*)d_in[12];
    const float* freq = (const float*)d_in[13];
    const void*  src  = d_in[14];
    const void*  dst  = d_in[15];
    const void*  etp  = d_in[16];
    const void*  sidx = d_in[17];
    const void*  ridx = d_in[18];
    float* out = (float*)d_out;

    float* h1  = out;             // [0, 20M)
    float* agg = out + AGG_OFF;   // [20M, 40M); later h2 in place
    float* hT  = out;             // [0, 20M), transposed h_final (after h1 dead)

    const int TRANS_SMEM  = (32 * 400 + 2 * 4 * 800) * (int)sizeof(float);    // 76.8 KB
    const int SCORES_SMEM = (64 * 202 + 64 * 204) * (int)sizeof(float);       // 103.9 KB
    cudaFuncSetAttribute(k_transform, cudaFuncAttributeMaxDynamicSharedMemorySize, TRANS_SMEM);
    cudaFuncSetAttribute(k_scores,    cudaFuncAttributeMaxDynamicSharedMemorySize, SCORES_SMEM);

    const int zgrid = (NUM_E * H4 + 255) / 256;

    k_zero_init<<<zgrid, 256>>>(agg);
    k_detect<<<1, 32>>>((const unsigned int*)src);

    // layer 1
    k_edges<<<NEDGE / 8, 256>>>(src, dst, etp, rel, ent, agg, 1);
    k_transform<<<NUM_E / 32, 400, TRANS_SMEM>>>(ent, Wn1, Wl1, agg, h1);

    // layer 2 (h2 in place over agg)
    k_zero_agg<<<zgrid, 256>>>(agg);
    k_edges<<<NEDGE / 8, 256>>>(src, dst, etp, rel, h1, agg, 0);
    k_transform<<<NUM_E / 32, 400, TRANS_SMEM>>>(h1, Wn2, Wl2, agg, agg);

    // fused gate + blend + transpose into hT = out[0,20M)
    k_blendT<<<NUM_E / 32, 256>>>(agg /*h2*/, ent, gth, gw, gb, hT);

    // ConvE head
    k_bnstats<<<BATCH, 256>>>(hT, rel, freq, sidx, ridx);
    k_q<<<(BATCH * HDIM + 255) / 256, 256>>>(hT, rel, freq, sidx, ridx, bng, bnb, cw, cb);

    // scores in place over the whole output (panel-exclusive blocks)
    k_scores<<<(NUM_E + 63) / 64, 256, SCORES_SMEM>>>(out);
}